// round 7
// baseline (speedup 1.0000x reference)
#include <cuda_runtime.h>
#include <cuda_bf16.h>

// Problem constants
#define BATCH 4096
#define SEQ   512
#define HID   32
#define NB    4            // batch elements per block (2 per warp epilogue)
#define WPB   2            // warps per block (k-split cooperators)

#define L2E   1.4426950408889634f    // log2(e)

using u64 = unsigned long long;

// ---- packed f32x2 helpers (FFMA2/FADD2 path, PTX-only) ----
__device__ __forceinline__ u64 pack2(float lo, float hi) {
    u64 r; asm("mov.b64 %0, {%1, %2};" : "=l"(r) : "f"(lo), "f"(hi)); return r;
}
__device__ __forceinline__ void unpack2(u64 v, float& lo, float& hi) {
    asm("mov.b64 {%0, %1}, %2;" : "=f"(lo), "=f"(hi) : "l"(v));
}
__device__ __forceinline__ u64 fma2(u64 a, u64 b, u64 c) {
    u64 d; asm("fma.rn.f32x2 %0, %1, %2, %3;" : "=l"(d) : "l"(a), "l"(b), "l"(c)); return d;
}
__device__ __forceinline__ u64 add2(u64 a, u64 b) {
    u64 d; asm("add.rn.f32x2 %0, %1, %2;" : "=l"(d) : "l"(a), "l"(b)); return d;
}
__device__ __forceinline__ float lo2(u64 v) {
    float lo, hi; unpack2(v, lo, hi); return lo;
}

// ---- raw MUFU helpers ----
__device__ __forceinline__ float ex2f(float v) {
    float r; asm("ex2.approx.f32 %0, %1;" : "=f"(r) : "f"(v)); return r;
}
__device__ __forceinline__ float rcpf(float v) {
    float r; asm("rcp.approx.f32 %0, %1;" : "=f"(r) : "f"(v)); return r;
}
// a_scaled = -log2(e) * a   -> sigmoid(a)
__device__ __forceinline__ float sig_s(float a_scaled) {
    return rcpf(1.0f + ex2f(a_scaled));
}
// a_scaled = -2*log2(e) * a -> tanh(a)
__device__ __forceinline__ float tanh_s(float a_scaled) {
    return fmaf(2.0f, rcpf(1.0f + ex2f(a_scaled)), -1.0f);
}
// exact-path (same units) activations for the tail section
__device__ __forceinline__ float sigf(float v) {
    return __fdividef(1.0f, 1.0f + __expf(-v));
}
__device__ __forceinline__ float tanhf_fast(float v) {
    return __fdividef(2.0f, 1.0f + __expf(-2.0f * v)) - 1.0f;
}

// ---------------------------------------------------------------------------
// Fused kernel, 2-warp k-split per block.
// Block handles NB=4 batches. Warp w owns k-range [16w, 16w+16) with those
// weight slices in registers; it computes partial gate sums for all 4 batches
// (128 FFMA2 per step). Partials for the partner's epilogue-batches go
// through smem; each warp runs the nonlinear epilogue for its 2 batches.
// ---------------------------------------------------------------------------
__global__ void __launch_bounds__(WPB * 32) lstm_kernel(
    const float* __restrict__ x,
    const float* __restrict__ h0,   const float* __restrict__ c0,
    const float* __restrict__ Wih1, const float* __restrict__ Whh1,
    const float* __restrict__ bih1, const float* __restrict__ bhh1,
    const float* __restrict__ Wih2, const float* __restrict__ Whh2,
    const float* __restrict__ bih2, const float* __restrict__ bhh2,
    const float* __restrict__ Wfc,  const float* __restrict__ bfc,
    float* __restrict__ out)
{
    __shared__ ulonglong2 Hs[2][NB / 2][32];  // [buf][pair g][k]=((h2g,h2g),(h2g1,h2g1))
    __shared__ ulonglong2 Ps[WPB][2][32];     // [writer warp][partner batch i][j]=(aIF,aGO)

    const int j  = threadIdx.x & 31;     // lane = hidden unit
    const int w  = threadIdx.x >> 5;     // warp in block (k-half owner)
    const int b0 = blockIdx.x * NB;
    const int kb = 16 * w;               // my k-range base

    // ---- weights for my k-half: 16 slices of scaled Whh1 into registers ----
    u64 wIFr[16], wGOr[16];
    {
        const float4* W1v = reinterpret_cast<const float4*>(Whh1);
        #pragma unroll
        for (int q = 0; q < 4; q++) {           // quads within my k-half
            int qq = 4 * w + q;                 // global float4 index (k = 4*qq..)
            float4 wi = W1v[(0  + j) * 8 + qq];
            float4 wf = W1v[(32 + j) * 8 + qq];
            float4 wg = W1v[(64 + j) * 8 + qq];
            float4 wo = W1v[(96 + j) * 8 + qq];
            wIFr[4 * q + 0] = pack2(-L2E * wi.x, -L2E * wf.x);
            wIFr[4 * q + 1] = pack2(-L2E * wi.y, -L2E * wf.y);
            wIFr[4 * q + 2] = pack2(-L2E * wi.z, -L2E * wf.z);
            wIFr[4 * q + 3] = pack2(-L2E * wi.w, -L2E * wf.w);
            wGOr[4 * q + 0] = pack2(-2.0f * L2E * wg.x, -L2E * wo.x);
            wGOr[4 * q + 1] = pack2(-2.0f * L2E * wg.y, -L2E * wo.y);
            wGOr[4 * q + 2] = pack2(-2.0f * L2E * wg.z, -L2E * wo.z);
            wGOr[4 * q + 3] = pack2(-2.0f * L2E * wg.w, -L2E * wo.w);
        }
    }

    // Per-lane constants (scaled); used only for my 2 epilogue batches
    const u64 biasIF = pack2(-L2E        * (bih1[0  + j] + bhh1[0  + j]),
                             -L2E        * (bih1[32 + j] + bhh1[32 + j]));
    const u64 biasGO = pack2(-2.0f * L2E * (bih1[64 + j] + bhh1[64 + j]),
                             -L2E        * (bih1[96 + j] + bhh1[96 + j]));
    const u64 wihIF  = pack2(-L2E        * Wih1[0  + j],
                             -L2E        * Wih1[32 + j]);
    const u64 wihGO  = pack2(-2.0f * L2E * Wih1[64 + j],
                             -L2E        * Wih1[96 + j]);

    // My 2 epilogue batches: 2w, 2w+1. Carry their c in registers.
    float c[2];
    c[0] = c0[(b0 + 2 * w)     * HID + j];
    c[1] = c0[(b0 + 2 * w + 1) * HID + j];

    // Init Hs pair-group w (my batches)
    {
        float ha = h0[(b0 + 2 * w)     * HID + j];
        float hb = h0[(b0 + 2 * w + 1) * HID + j];
        ulonglong2 hq;
        hq.x = pack2(ha, ha);
        hq.y = pack2(hb, hb);
        Hs[0][w][j] = hq;
    }

    // lanes 0,1 of warp w hold x[t][b0+2w+lane]; prefetch one step ahead
    float xc = (j < 2) ? x[b0 + 2 * w + j] : 0.0f;
    __syncthreads();

    // ---------------- 512-step recurrence ----------------
    #pragma unroll 1
    for (int t = 0; t < SEQ; t++) {
        const int rb = t & 1;

        float xn = 0.0f;
        if (j < 2 && t + 1 < SEQ) xn = x[(t + 1) * BATCH + b0 + 2 * w + j];

        // Accumulators for all 4 batches over MY k-half.
        // Own batches (2w, 2w+1) start with bias + x*wih; partner's start at 0.
        u64 aIF[NB], aGO[NB];
        {
            float x0 = __shfl_sync(0xffffffffu, xc, 0);
            float x1 = __shfl_sync(0xffffffffu, xc, 1);
            u64 xd0 = pack2(x0, x0);
            u64 xd1 = pack2(x1, x1);
            aIF[2 * w]     = fma2(xd0, wihIF, biasIF);
            aGO[2 * w]     = fma2(xd0, wihGO, biasGO);
            aIF[2 * w + 1] = fma2(xd1, wihIF, biasIF);
            aGO[2 * w + 1] = fma2(xd1, wihGO, biasGO);
            int pw = 1 - w;
            aIF[2 * pw]     = 0ull; aGO[2 * pw]     = 0ull;
            aIF[2 * pw + 1] = 0ull; aGO[2 * pw + 1] = 0ull;
        }

        // Partial matvec over my 16 k's: per k, 2 broadcast LDS.128 + 8 FFMA2
        #pragma unroll
        for (int kk = 0; kk < 16; kk++) {
            int k = kb + kk;
            u64 wIF = wIFr[kk];
            u64 wGO = wGOr[kk];
            ulonglong2 hq0 = Hs[rb][0][k];
            ulonglong2 hq1 = Hs[rb][1][k];
            aIF[0] = fma2(hq0.x, wIF, aIF[0]);
            aGO[0] = fma2(hq0.x, wGO, aGO[0]);
            aIF[1] = fma2(hq0.y, wIF, aIF[1]);
            aGO[1] = fma2(hq0.y, wGO, aGO[1]);
            aIF[2] = fma2(hq1.x, wIF, aIF[2]);
            aGO[2] = fma2(hq1.x, wGO, aGO[2]);
            aIF[3] = fma2(hq1.y, wIF, aIF[3]);
            aGO[3] = fma2(hq1.y, wGO, aGO[3]);
        }

        // Exchange: store my partials for the partner's 2 batches
        {
            int pw = 1 - w;
            ulonglong2 p0, p1;
            p0.x = aIF[2 * pw];     p0.y = aGO[2 * pw];
            p1.x = aIF[2 * pw + 1]; p1.y = aGO[2 * pw + 1];
            Ps[w][0][j] = p0;
            Ps[w][1][j] = p1;
        }
        __syncthreads();

        // Combine + epilogue for my 2 batches
        float hn0, hn1;
        {
            int pw = 1 - w;
            ulonglong2 q0 = Ps[pw][0][j];   // partner's partial for my batch 2w
            ulonglong2 q1 = Ps[pw][1][j];   // ... for my batch 2w+1
            u64 sIF0 = add2(aIF[2 * w],     q0.x);
            u64 sGO0 = add2(aGO[2 * w],     q0.y);
            u64 sIF1 = add2(aIF[2 * w + 1], q1.x);
            u64 sGO1 = add2(aGO[2 * w + 1], q1.y);

            float ai, af, ag, ao;
            unpack2(sIF0, ai, af);
            unpack2(sGO0, ag, ao);
            float ig = sig_s(ai), fg = sig_s(af);
            float gg = tanh_s(ag), og = sig_s(ao);
            c[0] = fmaf(fg, c[0], ig * gg);
            hn0  = og * tanh_s(c[0] * (-2.0f * L2E));

            unpack2(sIF1, ai, af);
            unpack2(sGO1, ag, ao);
            ig = sig_s(ai); fg = sig_s(af);
            gg = tanh_s(ag); og = sig_s(ao);
            c[1] = fmaf(fg, c[1], ig * gg);
            hn1  = og * tanh_s(c[1] * (-2.0f * L2E));
        }

        // Publish my batches' new h (duplicated pairs) into the other buffer
        {
            ulonglong2 hq;
            hq.x = pack2(hn0, hn0);
            hq.y = pack2(hn1, hn1);
            Hs[rb ^ 1][w][j] = hq;
        }
        xc = xn;
        __syncthreads();
    }

    // ---------------- inline tail: cell 2 + FC for my 2 batches ----------------
    // SEQ even -> final h is in Hs[0]; c[] holds my batches' final cell state.
    float a2i[2], a2f[2], a2g[2], a2o[2];
    {
        float bi2 = bih2[0  + j] + bhh2[0  + j];
        float bf2 = bih2[32 + j] + bhh2[32 + j];
        float bg2 = bih2[64 + j] + bhh2[64 + j];
        float bo2 = bih2[96 + j] + bhh2[96 + j];
        a2i[0] = a2i[1] = bi2;
        a2f[0] = a2f[1] = bf2;
        a2g[0] = a2g[1] = bg2;
        a2o[0] = a2o[1] = bo2;
    }
    {
        const float4* Wi2v = reinterpret_cast<const float4*>(Wih2);
        const float4* Wh2v = reinterpret_cast<const float4*>(Whh2);
        #pragma unroll
        for (int q = 0; q < 8; q++) {
            float4 wi = Wi2v[(0  + j) * 8 + q], hi_ = Wh2v[(0  + j) * 8 + q];
            float4 wf = Wi2v[(32 + j) * 8 + q], hf_ = Wh2v[(32 + j) * 8 + q];
            float4 wg = Wi2v[(64 + j) * 8 + q], hg_ = Wh2v[(64 + j) * 8 + q];
            float4 wo = Wi2v[(96 + j) * 8 + q], ho_ = Wh2v[(96 + j) * 8 + q];
            float ci2[4] = { wi.x + hi_.x, wi.y + hi_.y, wi.z + hi_.z, wi.w + hi_.w };
            float cf2[4] = { wf.x + hf_.x, wf.y + hf_.y, wf.z + hf_.z, wf.w + hf_.w };
            float cg2[4] = { wg.x + hg_.x, wg.y + hg_.y, wg.z + hg_.z, wg.w + hg_.w };
            float co2[4] = { wo.x + ho_.x, wo.y + ho_.y, wo.z + ho_.z, wo.w + ho_.w };
            #pragma unroll
            for (int kk = 0; kk < 4; kk++) {
                int k = 4 * q + kk;
                ulonglong2 hq = Hs[0][w][k];        // my pair group
                float hk0 = lo2(hq.x);
                float hk1 = lo2(hq.y);
                a2i[0] = fmaf(hk0, ci2[kk], a2i[0]);
                a2f[0] = fmaf(hk0, cf2[kk], a2f[0]);
                a2g[0] = fmaf(hk0, cg2[kk], a2g[0]);
                a2o[0] = fmaf(hk0, co2[kk], a2o[0]);
                a2i[1] = fmaf(hk1, ci2[kk], a2i[1]);
                a2f[1] = fmaf(hk1, cf2[kk], a2f[1]);
                a2g[1] = fmaf(hk1, cg2[kk], a2g[1]);
                a2o[1] = fmaf(hk1, co2[kk], a2o[1]);
            }
        }
    }

    const float wfc_j = Wfc[j];
    const float bfc0  = bfc[0];
    #pragma unroll
    for (int b = 0; b < 2; b++) {
        float cn  = fmaf(sigf(a2f[b]), c[b], sigf(a2i[b]) * tanhf_fast(a2g[b]));
        float h1f = sigf(a2o[b]) * tanhf_fast(cn);
        float v = h1f * wfc_j;
        #pragma unroll
        for (int m = 16; m > 0; m >>= 1)
            v += __shfl_xor_sync(0xffffffffu, v, m);
        if (j == 0) out[b0 + 2 * w + b] = v + bfc0;
    }
}

// ---------------------------------------------------------------------------
// kernel_launch: single fused launch (graph-capturable)
// Input order: x,h0,c0,h1,c1,Wih1,Whh1,bih1,bhh1,Wih2,Whh2,bih2,bhh2,Wfc,bfc
// ---------------------------------------------------------------------------
extern "C" void kernel_launch(void* const* d_in, const int* in_sizes, int n_in,
                              void* d_out, int out_size)
{
    const float* x    = (const float*)d_in[0];
    const float* h0   = (const float*)d_in[1];
    const float* c0   = (const float*)d_in[2];
    const float* Wih1 = (const float*)d_in[5];
    const float* Whh1 = (const float*)d_in[6];
    const float* bih1 = (const float*)d_in[7];
    const float* bhh1 = (const float*)d_in[8];
    const float* Wih2 = (const float*)d_in[9];
    const float* Whh2 = (const float*)d_in[10];
    const float* bih2 = (const float*)d_in[11];
    const float* bhh2 = (const float*)d_in[12];
    const float* Wfc  = (const float*)d_in[13];
    const float* bfc  = (const float*)d_in[14];
    float* out = (float*)d_out;

    lstm_kernel<<<BATCH / NB, WPB * 32>>>(x, h0, c0, Wih1, Whh1, bih1, bhh1,
                                          Wih2, Whh2, bih2, bhh2, Wfc, bfc, out);
}

// round 8
// speedup vs baseline: 2.0061x; 2.0061x over previous
#include <cuda_runtime.h>
#include <cuda_bf16.h>

// Problem constants
#define BATCH 4096
#define SEQ   512
#define HID   32
#define NB    4            // batch elements per warp; 1024 one-warp blocks

using u64 = unsigned long long;

// ---- packed f32x2 helpers (FFMA2 path, PTX-only) ----
__device__ __forceinline__ u64 pack2(float lo, float hi) {
    u64 r; asm("mov.b64 %0, {%1, %2};" : "=l"(r) : "f"(lo), "f"(hi)); return r;
}
__device__ __forceinline__ void unpack2(u64 v, float& lo, float& hi) {
    asm("mov.b64 {%0, %1}, %2;" : "=f"(lo), "=f"(hi) : "l"(v));
}
__device__ __forceinline__ u64 fma2(u64 a, u64 b, u64 c) {
    u64 d; asm("fma.rn.f32x2 %0, %1, %2, %3;" : "=l"(d) : "l"(a), "l"(b), "l"(c)); return d;
}
__device__ __forceinline__ float lo2(u64 v) {
    float lo, hi; unpack2(v, lo, hi); return lo;
}

// ---- hardware tanh (MUFU.TANH, sm_75+) ----
__device__ __forceinline__ float tanh_hw(float v) {
    float r; asm("tanh.approx.f32 %0, %1;" : "=f"(r) : "f"(v)); return r;
}
// preactivation already halved (0.5 folded into weights): sigmoid(a) with in = a/2
__device__ __forceinline__ float sig_h(float half_a) {
    return fmaf(0.5f, tanh_hw(half_a), 0.5f);
}

// ---- exact-path activations for the tail section (unchanged precision) ----
__device__ __forceinline__ float sigf(float v) {
    return __fdividef(1.0f, 1.0f + __expf(-v));
}
__device__ __forceinline__ float tanhf_fast(float v) {
    return __fdividef(2.0f, 1.0f + __expf(-2.0f * v)) - 1.0f;
}

// ---------------------------------------------------------------------------
// Single fused kernel: inline weight pack -> 512-step scan -> cell2 + FC.
// 1024 one-warp blocks; lane = hidden unit j; NB=4 batches per warp.
// All Whh1 weights in registers (64 u64 pairs / lane), scaled so that the
// i,f,o gates produce a/2 (for the 0.5*tanh(a/2)+0.5 sigmoid form) and g
// produces a (for direct tanh). Activations use MUFU.TANH.
// ---------------------------------------------------------------------------
__global__ void __launch_bounds__(32) lstm_kernel(
    const float* __restrict__ x,
    const float* __restrict__ h0,   const float* __restrict__ c0,
    const float* __restrict__ Wih1, const float* __restrict__ Whh1,
    const float* __restrict__ bih1, const float* __restrict__ bhh1,
    const float* __restrict__ Wih2, const float* __restrict__ Whh2,
    const float* __restrict__ bih2, const float* __restrict__ bhh2,
    const float* __restrict__ Wfc,  const float* __restrict__ bfc,
    float* __restrict__ out)
{
    __shared__ ulonglong2 Hs[2][NB / 2][32];   // [buf][pair][k] = ((hA,hA),(hB,hB))

    const int j  = threadIdx.x;          // lane = hidden unit
    const int b0 = blockIdx.x * NB;

    // ---- inline pack: all 32 k-slices of scaled Whh1 into registers ----
    // i,f,o rows scaled by 0.5 (sigmoid-as-tanh form); g row unscaled.
    u64 wIFr[32], wGOr[32];
    {
        const float4* W1v = reinterpret_cast<const float4*>(Whh1);
        #pragma unroll
        for (int q = 0; q < 8; q++) {
            float4 wi = W1v[(0  + j) * 8 + q];
            float4 wf = W1v[(32 + j) * 8 + q];
            float4 wg = W1v[(64 + j) * 8 + q];
            float4 wo = W1v[(96 + j) * 8 + q];
            wIFr[4 * q + 0] = pack2(0.5f * wi.x, 0.5f * wf.x);
            wIFr[4 * q + 1] = pack2(0.5f * wi.y, 0.5f * wf.y);
            wIFr[4 * q + 2] = pack2(0.5f * wi.z, 0.5f * wf.z);
            wIFr[4 * q + 3] = pack2(0.5f * wi.w, 0.5f * wf.w);
            wGOr[4 * q + 0] = pack2(wg.x, 0.5f * wo.x);
            wGOr[4 * q + 1] = pack2(wg.y, 0.5f * wo.y);
            wGOr[4 * q + 2] = pack2(wg.z, 0.5f * wo.z);
            wGOr[4 * q + 3] = pack2(wg.w, 0.5f * wo.w);
        }
    }

    // Per-lane constants: combined bias and input weight, gate-paired, scaled
    const u64 biasIF = pack2(0.5f * (bih1[0  + j] + bhh1[0  + j]),
                             0.5f * (bih1[32 + j] + bhh1[32 + j]));
    const u64 biasGO = pack2(       (bih1[64 + j] + bhh1[64 + j]),
                             0.5f * (bih1[96 + j] + bhh1[96 + j]));
    const u64 wihIF  = pack2(0.5f * Wih1[0  + j],
                             0.5f * Wih1[32 + j]);
    const u64 wihGO  = pack2(       Wih1[64 + j],
                             0.5f * Wih1[96 + j]);

    // Carry c in registers; h lives in the smem stage
    float c[NB];
    #pragma unroll
    for (int b = 0; b < NB; b++) c[b] = c0[(b0 + b) * HID + j];

    #pragma unroll
    for (int g = 0; g < NB / 2; g++) {
        float ha = h0[(b0 + 2 * g)     * HID + j];
        float hb = h0[(b0 + 2 * g + 1) * HID + j];
        ulonglong2 hq;
        hq.x = pack2(ha, ha);
        hq.y = pack2(hb, hb);
        Hs[0][g][j] = hq;
    }

    // x[t][b0..b0+3] is contiguous: every lane issues the same LDG.128
    // (broadcast, 1 wavefront). Prefetch one step ahead.
    float4 xc = *reinterpret_cast<const float4*>(&x[b0]);
    __syncwarp();

    // ---------------- 512-step recurrence ----------------
    #pragma unroll 1
    for (int t = 0; t < SEQ; t++) {
        const int rb = t & 1;

        float4 xn = make_float4(0.f, 0.f, 0.f, 0.f);
        if (t + 1 < SEQ)
            xn = *reinterpret_cast<const float4*>(&x[(t + 1) * BATCH + b0]);

        u64 aIF[NB], aGO[NB];
        {
            u64 xd0 = pack2(xc.x, xc.x);
            u64 xd1 = pack2(xc.y, xc.y);
            u64 xd2 = pack2(xc.z, xc.z);
            u64 xd3 = pack2(xc.w, xc.w);
            aIF[0] = fma2(xd0, wihIF, biasIF);  aGO[0] = fma2(xd0, wihGO, biasGO);
            aIF[1] = fma2(xd1, wihIF, biasIF);  aGO[1] = fma2(xd1, wihGO, biasGO);
            aIF[2] = fma2(xd2, wihIF, biasIF);  aGO[2] = fma2(xd2, wihGO, biasGO);
            aIF[3] = fma2(xd3, wihIF, biasIF);  aGO[3] = fma2(xd3, wihGO, biasGO);
        }

        // recurrent matvec: per k, 2 broadcast LDS.128 + 8 FFMA2, weights all
        // from registers.
        #pragma unroll
        for (int k = 0; k < 32; k++) {
            u64 wIF = wIFr[k];
            u64 wGO = wGOr[k];
            #pragma unroll
            for (int g = 0; g < NB / 2; g++) {
                ulonglong2 hq = Hs[rb][g][k];     // broadcast, pre-paired
                aIF[2 * g]     = fma2(hq.x, wIF, aIF[2 * g]);
                aGO[2 * g]     = fma2(hq.x, wGO, aGO[2 * g]);
                aIF[2 * g + 1] = fma2(hq.y, wIF, aIF[2 * g + 1]);
                aGO[2 * g + 1] = fma2(hq.y, wGO, aGO[2 * g + 1]);
            }
        }

        float hn[NB];
        #pragma unroll
        for (int b = 0; b < NB; b++) {
            float ai, af, ag, ao;
            unpack2(aIF[b], ai, af);      // ai, af pre-halved
            unpack2(aGO[b], ag, ao);      // ag full, ao pre-halved
            float ig = sig_h(ai);
            float fg = sig_h(af);
            float gg = tanh_hw(ag);
            float og = sig_h(ao);
            c[b]  = fmaf(fg, c[b], ig * gg);
            hn[b] = og * tanh_hw(c[b]);
        }

        #pragma unroll
        for (int g = 0; g < NB / 2; g++) {
            ulonglong2 hq;
            hq.x = pack2(hn[2 * g],     hn[2 * g]);
            hq.y = pack2(hn[2 * g + 1], hn[2 * g + 1]);
            Hs[rb ^ 1][g][j] = hq;
        }
        xc = xn;
        __syncwarp();
    }

    // ---------------- inline tail: cell 2 + FC (exact path) ----------------
    // SEQ even -> final h is in Hs[0]; c[] holds final cell state.
    float a2i[NB], a2f[NB], a2g[NB], a2o[NB];
    {
        float bi2 = bih2[0  + j] + bhh2[0  + j];
        float bf2 = bih2[32 + j] + bhh2[32 + j];
        float bg2 = bih2[64 + j] + bhh2[64 + j];
        float bo2 = bih2[96 + j] + bhh2[96 + j];
        #pragma unroll
        for (int b = 0; b < NB; b++) {
            a2i[b] = bi2; a2f[b] = bf2; a2g[b] = bg2; a2o[b] = bo2;
        }
    }
    {
        const float4* Wi2v = reinterpret_cast<const float4*>(Wih2);
        const float4* Wh2v = reinterpret_cast<const float4*>(Whh2);
        #pragma unroll
        for (int q = 0; q < 8; q++) {
            float4 wi = Wi2v[(0  + j) * 8 + q], hi_ = Wh2v[(0  + j) * 8 + q];
            float4 wf = Wi2v[(32 + j) * 8 + q], hf_ = Wh2v[(32 + j) * 8 + q];
            float4 wg = Wi2v[(64 + j) * 8 + q], hg_ = Wh2v[(64 + j) * 8 + q];
            float4 wo = Wi2v[(96 + j) * 8 + q], ho_ = Wh2v[(96 + j) * 8 + q];
            float ci2[4] = { wi.x + hi_.x, wi.y + hi_.y, wi.z + hi_.z, wi.w + hi_.w };
            float cf2[4] = { wf.x + hf_.x, wf.y + hf_.y, wf.z + hf_.z, wf.w + hf_.w };
            float cg2[4] = { wg.x + hg_.x, wg.y + hg_.y, wg.z + hg_.z, wg.w + hg_.w };
            float co2[4] = { wo.x + ho_.x, wo.y + ho_.y, wo.z + ho_.z, wo.w + ho_.w };
            #pragma unroll
            for (int kk = 0; kk < 4; kk++) {
                int k = 4 * q + kk;
                ulonglong2 hq0 = Hs[0][0][k];
                ulonglong2 hq1 = Hs[0][1][k];
                float hk[NB] = { lo2(hq0.x), lo2(hq0.y), lo2(hq1.x), lo2(hq1.y) };
                #pragma unroll
                for (int b = 0; b < NB; b++) {
                    a2i[b] = fmaf(hk[b], ci2[kk], a2i[b]);
                    a2f[b] = fmaf(hk[b], cf2[kk], a2f[b]);
                    a2g[b] = fmaf(hk[b], cg2[kk], a2g[b]);
                    a2o[b] = fmaf(hk[b], co2[kk], a2o[b]);
                }
            }
        }
    }

    const float wfc_j = Wfc[j];
    const float bfc0  = bfc[0];
    #pragma unroll
    for (int b = 0; b < NB; b++) {
        float cn  = fmaf(sigf(a2f[b]), c[b], sigf(a2i[b]) * tanhf_fast(a2g[b]));
        float h1f = sigf(a2o[b]) * tanhf_fast(cn);
        float v = h1f * wfc_j;
        #pragma unroll
        for (int m = 16; m > 0; m >>= 1)
            v += __shfl_xor_sync(0xffffffffu, v, m);
        if (j == 0) out[b0 + b] = v + bfc0;
    }
}

// ---------------------------------------------------------------------------
// kernel_launch: single fused launch (graph-capturable)
// Input order: x,h0,c0,h1,c1,Wih1,Whh1,bih1,bhh1,Wih2,Whh2,bih2,bhh2,Wfc,bfc
// ---------------------------------------------------------------------------
extern "C" void kernel_launch(void* const* d_in, const int* in_sizes, int n_in,
                              void* d_out, int out_size)
{
    const float* x    = (const float*)d_in[0];
    const float* h0   = (const float*)d_in[1];
    const float* c0   = (const float*)d_in[2];
    const float* Wih1 = (const float*)d_in[5];
    const float* Whh1 = (const float*)d_in[6];
    const float* bih1 = (const float*)d_in[7];
    const float* bhh1 = (const float*)d_in[8];
    const float* Wih2 = (const float*)d_in[9];
    const float* Whh2 = (const float*)d_in[10];
    const float* bih2 = (const float*)d_in[11];
    const float* bhh2 = (const float*)d_in[12];
    const float* Wfc  = (const float*)d_in[13];
    const float* bfc  = (const float*)d_in[14];
    float* out = (float*)d_out;

    lstm_kernel<<<BATCH / NB, 32>>>(x, h0, c0, Wih1, Whh1, bih1, bhh1,
                                    Wih2, Whh2, bih2, bhh2, Wfc, bfc, out);
}